// round 10
// baseline (speedup 1.0000x reference)
#include <cuda_runtime.h>
#include <cuda_bf16.h>
#include <cstdint>

#define B_N 65536
#define X_N 362
#define GRID_S 19

// layer2: D[.x400] = h1[.x112] @ W2t ; layer3: D[.x112] = h2[.x400] @ W3t
#define KT2 7     // layer2 k-tiles (112/16)
#define KT3 25    // layer3 k-tiles (400/16) == layer2 nt-pairs
#define NP3 7     // layer3 nt-pairs (14/2)

// ---- K2 dynamic smem layout (bytes) ----
#define WF2_OFF  0            // [kt3(25)][kt2(7)][lane(32)]{u32 x4} = 89600 B
#define WF3_OFF  89600        // [kt3(25)][p(7)][lane(32)]{u32 x4}   = 89600 B
#define ATT_OFF  179200       // 256*6 f32
#define META_OFF 185344       // 256 int
#define W1S_OFF  186368       // 600 f32
#define B1S_OFF  188768       // 100 f32
#define W4S_OFF  189168       // 600 f32
#define B2S_OFF  191568       // 400 f32
#define B3S_OFF  193168       // 100 f32
#define B4S_OFF  193568       // 6 f32
#define SMEM_SZ  193600

// ---- scratch (static device globals; no runtime allocation) ----
__device__ int      g_cnt[3];
__device__ int      g_meta[3 * B_N];
__device__ float    g_att[3 * B_N * 6];
__device__ uint32_t g_w2f[3 * KT3 * KT2 * 128];   // uint4-packed nt-pair B fragments
__device__ uint32_t g_w3f[3 * KT3 * NP3 * 128];

// ---- helpers ----
static __device__ __forceinline__ uint32_t cvt_bf16x2(float lo, float hi) {
    uint32_t r;
    asm("cvt.rn.bf16x2.f32 %0, %1, %2;" : "=r"(r) : "f"(hi), "f"(lo));   // low half = lo
    return r;
}
static __device__ __forceinline__ void mma16816(float *c, const uint32_t *a,
                                                uint32_t b0, uint32_t b1) {
    asm volatile(
        "mma.sync.aligned.m16n8k16.row.col.f32.bf16.bf16.f32 "
        "{%0,%1,%2,%3}, {%4,%5,%6,%7}, {%8,%9}, {%0,%1,%2,%3};"
        : "+f"(c[0]), "+f"(c[1]), "+f"(c[2]), "+f"(c[3])
        : "r"(a[0]), "r"(a[1]), "r"(a[2]), "r"(a[3]), "r"(b0), "r"(b1));
}

// ---- K0: build uint4-packed B-fragment images (zero-padded) + reset counters ----
__global__ void __launch_bounds__(256) wprep_kernel(const float *__restrict__ W2,
                                                    const float *__restrict__ W3) {
    if (blockIdx.x == 0 && threadIdx.x < 3) g_cnt[threadIdx.x] = 0;
    int idx = blockIdx.x * 256 + threadIdx.x;
    if (idx < 67200) {                       // 3 * 25*7*128
        int a = idx / 22400, r = idx % 22400;
        int kt3 = r / 896, r2 = r % 896;
        int kt2 = r2 / 128, r3 = r2 % 128;
        int lane = r3 >> 2, u = r3 & 3;
        int gid = lane >> 2, tp = lane & 3;
        int nt = 2 * kt3 + (u >> 1), breg = u & 1;
        int n = nt * 8 + gid;                 // < 400
        int k = kt2 * 16 + tp * 2 + breg * 8; // pad k>=100
        float v0 = (k < 100) ? W2[a * 40000 + k * 400 + n] : 0.f;
        float v1 = (k + 1 < 100) ? W2[a * 40000 + (k + 1) * 400 + n] : 0.f;
        g_w2f[idx] = cvt_bf16x2(v0, v1);
    } else if (idx < 134400) {               // 3 * 25*7*128
        int i2 = idx - 67200;
        int a = i2 / 22400, r = i2 % 22400;
        int kt3 = r / 896, r2 = r % 896;
        int p = r2 / 128, r3 = r2 % 128;
        int lane = r3 >> 2, u = r3 & 3;
        int gid = lane >> 2, tp = lane & 3;
        int nt3 = 2 * p + (u >> 1), breg = u & 1;
        int n = nt3 * 8 + gid;                // pad n>=100
        int k = kt3 * 16 + tp * 2 + breg * 8; // < 400
        float v0 = (n < 100) ? W3[a * 40000 + k * 100 + n] : 0.f;
        float v1 = (n < 100) ? W3[a * 40000 + (k + 1) * 100 + n] : 0.f;
        g_w3f[i2] = cvt_bf16x2(v0, v1);
    }
}

// ---- K1: read-only argmax + gather + bucket (copy moved to K2) ----
__global__ void __launch_bounds__(1024) prep_kernel(const float *__restrict__ x,
                                                    const int *__restrict__ act) {
    __shared__ int   s_cnt[3], s_base[3];
    __shared__ int   s_a[32], s_slot[32], s_meta[32];
    __shared__ float s_att[32][6];

    int tid = threadIdx.x, lane = tid & 31, w = tid >> 5;
    if (tid < 3) s_cnt[tid] = 0;
    __syncthreads();

    // warp-per-row argmax; coalesced row-contiguous loads (allocate in L2 for K2 reuse)
    int row = blockIdx.x * 32 + w;
    const float2 *xr = reinterpret_cast<const float2 *>(x + (size_t)row * X_N);

    float2 vals[6];
    float bv = -3.4e38f;
#pragma unroll
    for (int j = 0; j < 6; j++) {
        int pi = lane + 32 * j;
        if (pi < 181) {                       // j<5 always; j==5 only lanes 0..20
            float2 v = xr[pi];
            vals[j] = v;
            bv = fmaxf(bv, fmaxf(v.x, v.y));
        }
    }
#pragma unroll
    for (int off = 16; off > 0; off >>= 1)
        bv = fmaxf(bv, __shfl_xor_sync(0xffffffffu, bv, off));
    // min global index matching bv (first-index tie policy, like jnp.argmax)
    int bi = 0x7fffffff;
#pragma unroll
    for (int j = 0; j < 6; j++) {
        int pi = lane + 32 * j;
        if (pi < 181) {
            if (vals[j].x == bv) bi = min(bi, 2 * pi);
            if (vals[j].y == bv) bi = min(bi, 2 * pi + 1);
        }
    }
#pragma unroll
    for (int off = 16; off > 0; off >>= 1)
        bi = min(bi, __shfl_xor_sync(0xffffffffu, bi, off));

    if (lane == 0) {
        int ptr = bi;
        int a   = act[row];
        const float *xp = x + (size_t)row * X_N;
        int il  = min(max(ptr - GRID_S, 1), X_N - 1);
        int ir  = min(max(ptr + GRID_S, 1), X_N - 1);
        int iu  = min(max(ptr - 1, 1), X_N - 1);
        int idn = min(max(ptr + 1, 1), X_N - 1);
        s_att[w][0] = xp[0];
        s_att[w][1] = bv;       // == xp[ptr]
        s_att[w][2] = xp[il];
        s_att[w][3] = xp[ir];
        s_att[w][4] = xp[iu];
        s_att[w][5] = xp[idn];
        s_meta[w] = row | (ptr << 16);
        s_a[w]    = a;
        s_slot[w] = atomicAdd(&s_cnt[a], 1);
    }
    __syncthreads();
    if (tid < 3) s_base[tid] = atomicAdd(&g_cnt[tid], s_cnt[tid]);
    __syncthreads();
    if (lane == 0) {
        int a = s_a[w];
        int g = s_base[a] + s_slot[w];
        g_meta[a * B_N + g] = s_meta[w];
        float *dst = &g_att[(size_t)(a * B_N + g) * 6];
#pragma unroll
        for (int j = 0; j < 6; j++) dst[j] = s_att[w][j];
    }
}

// ---- K2: fused mma MLP + overlapped out=x copy of owned rows + scatter ----
__global__ void __launch_bounds__(256, 1) mlp_kernel(
    const float *__restrict__ x,
    const float *__restrict__ W1, const float *__restrict__ b1,
    const float *__restrict__ b2, const float *__restrict__ b3,
    const float *__restrict__ W4, const float *__restrict__ b4,
    float *__restrict__ out) {
    int c0n = g_cnt[0], c1n = g_cnt[1], c2n = g_cnt[2];
    int t0 = (c0n + 255) >> 8, t1 = (c1n + 255) >> 8, t2 = (c2n + 255) >> 8;
    int bid = blockIdx.x;
    int a, tile, cnt;
    if (bid < t0)                { a = 0; tile = bid;            cnt = c0n; }
    else if (bid < t0 + t1)      { a = 1; tile = bid - t0;       cnt = c1n; }
    else if (bid < t0 + t1 + t2) { a = 2; tile = bid - t0 - t1;  cnt = c2n; }
    else return;
    int base = tile * 256;
    int nv   = min(256, cnt - base);

    extern __shared__ char smem[];
    const uint4 *wf2 = reinterpret_cast<const uint4 *>(smem + WF2_OFF);
    const uint4 *wf3 = reinterpret_cast<const uint4 *>(smem + WF3_OFF);
    float *att_s = reinterpret_cast<float *>(smem + ATT_OFF);
    int   *meta_s = reinterpret_cast<int *>(smem + META_OFF);
    float *w1s = reinterpret_cast<float *>(smem + W1S_OFF);
    float *b1s = reinterpret_cast<float *>(smem + B1S_OFF);
    float *w4s = reinterpret_cast<float *>(smem + W4S_OFF);
    float *b2s = reinterpret_cast<float *>(smem + B2S_OFF);
    float *b3s = reinterpret_cast<float *>(smem + B3S_OFF);
    float *b4s = reinterpret_cast<float *>(smem + B4S_OFF);

    int tid = threadIdx.x, lane = tid & 31, wid = tid >> 5;
    int gid = lane >> 2, tp = lane & 3;

    // ---- phase -1: copy owned rows out <= x (overlaps with weight loads + MLP) ----
    // Each row belongs to exactly one sample in exactly one CTA; scatter (end of
    // kernel, after __syncthreads) overwrites 6 entries of rows this CTA copied.
    for (int s = wid; s < nv; s += 8) {
        int row = g_meta[a * B_N + base + s] & 0xFFFF;
        const float2 *src = reinterpret_cast<const float2 *>(x + (size_t)row * X_N);
        float2 *dst = reinterpret_cast<float2 *>(out + (size_t)row * X_N);
        float2 tmp[6];
#pragma unroll
        for (int q = 0; q < 6; q++) {
            int pi = lane + 32 * q;
            if (pi < 181) tmp[q] = __ldcs(&src[pi]);
        }
#pragma unroll
        for (int q = 0; q < 6; q++) {
            int pi = lane + 32 * q;
            if (pi < 181) __stcs(&dst[pi], tmp[q]);
        }
    }

    // ---- phase 0: cooperative loads ----
    for (int t = tid; t < 1536; t += 256) {
        int s = t / 6;
        att_s[t] = (s < nv) ? g_att[(size_t)(a * B_N + base) * 6 + t] : 0.f;
    }
    if (tid < 256) meta_s[tid] = (tid < nv) ? g_meta[a * B_N + base + tid] : 0;
    for (int t = tid; t < 600; t += 256) { w1s[t] = W1[a * 600 + t]; w4s[t] = W4[a * 600 + t]; }
    if (tid < 100) { b1s[tid] = b1[a * 100 + tid]; b3s[tid] = b3[a * 100 + tid]; }
    for (int t = tid; t < 400; t += 256) b2s[t] = b2[a * 400 + t];
    if (tid < 6) b4s[tid] = b4[a * 6 + tid];
    {
        const uint4 *s2 = reinterpret_cast<const uint4 *>(g_w2f + a * 22400);
        uint4 *d2 = reinterpret_cast<uint4 *>(smem + WF2_OFF);
        for (int i = tid; i < 5600; i += 256) d2[i] = s2[i];
        const uint4 *s3 = reinterpret_cast<const uint4 *>(g_w3f + a * 22400);
        uint4 *d3 = reinterpret_cast<uint4 *>(smem + WF3_OFF);
        for (int i = tid; i < 5600; i += 256) d3[i] = s3[i];
    }
    __syncthreads();

    // ---- layer 1: h1 directly into A-fragments for both m-tiles ----
    uint32_t a2[2][KT2][4];
#pragma unroll
    for (int t = 0; t < 2; t++) {
        int mt = wid * 2 + t;
        int r0 = mt * 16 + gid, r1 = r0 + 8;
        float at0[6], at1[6];
#pragma unroll
        for (int j = 0; j < 6; j++) { at0[j] = att_s[r0 * 6 + j]; at1[j] = att_s[r1 * 6 + j]; }
#pragma unroll
        for (int kt = 0; kt < KT2; kt++) {
            float h0[4], h1v[4];
            int ks0 = kt * 16 + tp * 2;
#pragma unroll
            for (int q = 0; q < 4; q++) {
                int k = ks0 + (q >> 1) * 8 + (q & 1);
                float v0 = 0.f, v1 = 0.f;
                if (k < 100) {
                    float acc0 = b1s[k], acc1 = b1s[k];
#pragma unroll
                    for (int j = 0; j < 6; j++) {
                        float wv = w1s[j * 100 + k];
                        acc0 = fmaf(at0[j], wv, acc0);
                        acc1 = fmaf(at1[j], wv, acc1);
                    }
                    v0 = fmaxf(acc0, 0.f);
                    v1 = fmaxf(acc1, 0.f);
                }
                h0[q] = v0; h1v[q] = v1;
            }
            a2[t][kt][0] = cvt_bf16x2(h0[0], h0[1]);
            a2[t][kt][1] = cvt_bf16x2(h1v[0], h1v[1]);
            a2[t][kt][2] = cvt_bf16x2(h0[2], h0[3]);
            a2[t][kt][3] = cvt_bf16x2(h1v[2], h1v[3]);
        }
    }

    // ---- fused layers 2+3: per kt3, compute layer2 nt-pair then feed 14 layer3 mmas ----
    float c3[2][14][4];
#pragma unroll
    for (int t = 0; t < 2; t++)
#pragma unroll
        for (int nt = 0; nt < 14; nt++) {
            int n0 = nt * 8 + tp * 2;
            float bl = (n0 < 100) ? b3s[n0] : 0.f;
            float bh = (n0 + 1 < 100) ? b3s[n0 + 1] : 0.f;
            c3[t][nt][0] = bl; c3[t][nt][1] = bh; c3[t][nt][2] = bl; c3[t][nt][3] = bh;
        }

#pragma unroll 1
    for (int kt3 = 0; kt3 < KT3; kt3++) {
        float c2[2][2][4];
#pragma unroll
        for (int t = 0; t < 2; t++)
#pragma unroll
            for (int h = 0; h < 2; h++) {
                float2 bb = *reinterpret_cast<const float2 *>(b2s + (2 * kt3 + h) * 8 + tp * 2);
                c2[t][h][0] = bb.x; c2[t][h][1] = bb.y; c2[t][h][2] = bb.x; c2[t][h][3] = bb.y;
            }
#pragma unroll
        for (int kt2 = 0; kt2 < KT2; kt2++) {
            uint4 bf = wf2[(kt3 * KT2 + kt2) * 32 + lane];
            mma16816(c2[0][0], a2[0][kt2], bf.x, bf.y);
            mma16816(c2[0][1], a2[0][kt2], bf.z, bf.w);
            mma16816(c2[1][0], a2[1][kt2], bf.x, bf.y);
            mma16816(c2[1][1], a2[1][kt2], bf.z, bf.w);
        }
        uint32_t a3f[2][4];
#pragma unroll
        for (int t = 0; t < 2; t++) {
            a3f[t][0] = cvt_bf16x2(fmaxf(c2[t][0][0], 0.f), fmaxf(c2[t][0][1], 0.f));
            a3f[t][1] = cvt_bf16x2(fmaxf(c2[t][0][2], 0.f), fmaxf(c2[t][0][3], 0.f));
            a3f[t][2] = cvt_bf16x2(fmaxf(c2[t][1][0], 0.f), fmaxf(c2[t][1][1], 0.f));
            a3f[t][3] = cvt_bf16x2(fmaxf(c2[t][1][2], 0.f), fmaxf(c2[t][1][3], 0.f));
        }
#pragma unroll
        for (int p = 0; p < NP3; p++) {
            uint4 bf = wf3[(kt3 * NP3 + p) * 32 + lane];
            mma16816(c3[0][2 * p],     a3f[0], bf.x, bf.y);
            mma16816(c3[0][2 * p + 1], a3f[0], bf.z, bf.w);
            mma16816(c3[1][2 * p],     a3f[1], bf.x, bf.y);
            mma16816(c3[1][2 * p + 1], a3f[1], bf.z, bf.w);
        }
    }

    // ---- layer 4 + tp-reduction + ordered last-wins scatter (per m-tile) ----
    __syncthreads();   // all copy stores issued before any scatter store below
#pragma unroll
    for (int t = 0; t < 2; t++) {
        float p0[6] = {0, 0, 0, 0, 0, 0}, p1[6] = {0, 0, 0, 0, 0, 0};
#pragma unroll
        for (int nt = 0; nt < 14; nt++) {
            int n0 = nt * 8 + tp * 2;
            float v0 = fmaxf(c3[t][nt][0], 0.f), v1 = fmaxf(c3[t][nt][1], 0.f);
            float v2 = fmaxf(c3[t][nt][2], 0.f), v3 = fmaxf(c3[t][nt][3], 0.f);
            if (n0 < 100) {
                const float *wv = w4s + n0 * 6;
#pragma unroll
                for (int j = 0; j < 6; j++) {
                    p0[j] = fmaf(v0, wv[j], p0[j]);
                    p1[j] = fmaf(v2, wv[j], p1[j]);
                }
            }
            if (n0 + 1 < 100) {
                const float *wv = w4s + (n0 + 1) * 6;
#pragma unroll
                for (int j = 0; j < 6; j++) {
                    p0[j] = fmaf(v1, wv[j], p0[j]);
                    p1[j] = fmaf(v3, wv[j], p1[j]);
                }
            }
        }
#pragma unroll
        for (int j = 0; j < 6; j++) {
            p0[j] += __shfl_xor_sync(0xffffffffu, p0[j], 1);
            p0[j] += __shfl_xor_sync(0xffffffffu, p0[j], 2);
            p1[j] += __shfl_xor_sync(0xffffffffu, p1[j], 1);
            p1[j] += __shfl_xor_sync(0xffffffffu, p1[j], 2);
        }
        if (tp == 0) {
            int mt = wid * 2 + t;
#pragma unroll
            for (int h = 0; h < 2; h++) {
                int s = mt * 16 + gid + h * 8;
                float *pp = h ? p1 : p0;
                if (s < nv) {
                    int meta = meta_s[s];
                    int row  = meta & 0xFFFF;
                    int ptr  = meta >> 16;
                    float *orow = out + (size_t)row * X_N;
                    int idx[6];
                    idx[0] = 0;
                    idx[1] = ptr;
                    idx[2] = min(max(ptr - GRID_S, 1), X_N - 1);
                    idx[3] = min(max(ptr + GRID_S, 1), X_N - 1);
                    idx[4] = min(max(ptr - 1, 1), X_N - 1);
                    idx[5] = min(max(ptr + 1, 1), X_N - 1);
                    // program order within one thread => last-wins like reference loop
#pragma unroll
                    for (int j = 0; j < 6; j++)
                        orow[idx[j]] = att_s[s * 6 + j] + (pp[j] + b4s[j]);
                }
            }
        }
    }
}

// ---- launcher ----
extern "C" void kernel_launch(void *const *d_in, const int *in_sizes, int n_in,
                              void *d_out, int out_size) {
    const float *x  = (const float *)d_in[0];
    const float *W1 = (const float *)d_in[1];
    const float *b1 = (const float *)d_in[2];
    const float *W2 = (const float *)d_in[3];
    const float *b2 = (const float *)d_in[4];
    const float *W3 = (const float *)d_in[5];
    const float *b3 = (const float *)d_in[6];
    const float *W4 = (const float *)d_in[7];
    const float *b4 = (const float *)d_in[8];
    const int   *act = (const int *)d_in[9];
    float *out = (float *)d_out;

    cudaFuncSetAttribute(mlp_kernel, cudaFuncAttributeMaxDynamicSharedMemorySize, SMEM_SZ);

    wprep_kernel<<<(134400 + 255) / 256, 256>>>(W2, W3);
    prep_kernel<<<B_N / 32, 1024>>>(x, act);
    // worst-case tile count: 256 + 1 + 1
    mlp_kernel<<<258, 256, SMEM_SZ>>>(x, W1, b1, b2, b3, W4, b4, out);
}